// round 3
// baseline (speedup 1.0000x reference)
#include <cuda_runtime.h>
#include <cuda_bf16.h>
#include <cstdint>

#define NNODES 100000
#define NEDGES 1600000
#define NTOT   (NEDGES + NNODES)   // explicit edges + explicit self loops
#define FIN    128
#define FHID   128
#define FOUT   40

// ---------------- device scratch ----------------
__device__ float g_h1 [(size_t)NNODES * FHID];
__device__ float g_a1 [(size_t)NNODES * FHID];
__device__ float g_h1b[(size_t)NNODES * FHID];
__device__ float g_h2 [(size_t)NNODES * FOUT];
__device__ float g_a2 [(size_t)NNODES * FOUT];
__device__ int   g_src[NEDGES];
__device__ int   g_dst[NEDGES];
__device__ int   g_deg[NNODES];
__device__ float g_dis[NNODES];
__device__ float g_norm[NEDGES];
__device__ int   g_oddzero;
__device__ int   g_is64;

// ---------------- edge-index format detection (int32 vs int64) ----------------
__global__ void k_zflag() { g_oddzero = 0; }

__global__ void k_detect(const int* __restrict__ ei) {
    int i = blockIdx.x * blockDim.x + threadIdx.x;
    if (i < NEDGES) {
        // if the buffer is int64 little-endian, every odd 32-bit word is 0
        if (ei[2 * i + 1] == 0) atomicAdd(&g_oddzero, 1);
    }
}

__global__ void k_flag() { g_is64 = (g_oddzero > 1000000) ? 1 : 0; }

__global__ void k_repack(const int* __restrict__ ei) {
    int e = blockIdx.x * blockDim.x + threadIdx.x;
    if (e >= NEDGES) return;
    if (g_is64) {
        g_src[e] = ei[2 * e];                 // low word of row[e]
        g_dst[e] = ei[2 * NEDGES + 2 * e];    // low word of col[e]
    } else {
        g_src[e] = ei[e];                     // row (sources)
        g_dst[e] = ei[NEDGES + e];            // col (targets)
    }
}

// ---------------- degree / normalization (deg at targets, + self loop) -------
__global__ void k_init() {
    int v = blockIdx.x * blockDim.x + threadIdx.x;
    if (v < NNODES) g_deg[v] = 1;             // the appended self loop
}

__global__ void k_count() {
    int e = blockIdx.x * blockDim.x + threadIdx.x;
    if (e < NEDGES) atomicAdd(&g_deg[g_dst[e]], 1);
}

__global__ void k_dis() {
    int v = blockIdx.x * blockDim.x + threadIdx.x;
    if (v < NNODES) g_dis[v] = rsqrtf((float)g_deg[v]);
}

__global__ void k_norm() {
    int e = blockIdx.x * blockDim.x + threadIdx.x;
    if (e < NEDGES) g_norm[e] = g_dis[g_src[e]] * g_dis[g_dst[e]];
}

__global__ void k_zero() {
    size_t n1 = (size_t)NNODES * FHID;
    size_t n2 = (size_t)NNODES * FOUT;
    size_t i = (size_t)blockIdx.x * blockDim.x + threadIdx.x;
    size_t stride = (size_t)gridDim.x * blockDim.x;
    for (size_t k = i; k < n1; k += stride) g_a1[k] = 0.f;
    for (size_t k = i; k < n2; k += stride) g_a2[k] = 0.f;
}

// ---------------- GEMM1 (naive, literal): h1 = x @ W1 ----------------
__global__ __launch_bounds__(FHID) void k_gemm1(const float* __restrict__ x,
                                                const float* __restrict__ W1) {
    int n = blockIdx.x;
    int j = threadIdx.x;                      // 0..127 output feature
    const float* xr = x + (size_t)n * FIN;
    float acc = 0.f;
#pragma unroll 8
    for (int k = 0; k < FIN; k++) acc += xr[k] * W1[k * FHID + j];
    g_h1[(size_t)n * FHID + j] = acc;
}

// ---------------- edge scatter L1 (scalar atomics, explicit self loops) ------
__global__ void k_edge1() {
    int t = blockIdx.x * blockDim.x + threadIdx.x;
    if (t >= NTOT * FHID) return;
    int e = t >> 7;            // edge id
    int c = t & 127;           // feature
    int s, d; float w;
    if (e < NEDGES) { s = g_src[e]; d = g_dst[e]; w = g_norm[e]; }
    else { s = d = e - NEDGES; float dv = g_dis[s]; w = dv * dv; }
    atomicAdd(&g_a1[(size_t)d * FHID + c], w * g_h1[(size_t)s * FHID + c]);
}

// ---------------- post1: h1b = relu(a1 + b1) ----------------
__global__ void k_post1(const float* __restrict__ b1) {
    int i = blockIdx.x * blockDim.x + threadIdx.x;
    if (i >= NNODES * FHID) return;
    g_h1b[i] = fmaxf(g_a1[i] + b1[i & 127], 0.f);
}

// ---------------- GEMM2 (naive, literal): h2 = h1b @ W2 ----------------
__global__ __launch_bounds__(64) void k_gemm2(const float* __restrict__ W2) {
    int n = blockIdx.x;
    int j = threadIdx.x;                      // 0..63, active < 40
    if (j >= FOUT) return;
    const float* hr = g_h1b + (size_t)n * FHID;
    float acc = 0.f;
#pragma unroll 8
    for (int k = 0; k < FHID; k++) acc += hr[k] * W2[k * FOUT + j];
    g_h2[(size_t)n * FOUT + j] = acc;
}

// ---------------- edge scatter L2 (scalar atomics) ----------------
__global__ void k_edge2() {
    int t = blockIdx.x * blockDim.x + threadIdx.x;
    if (t >= NTOT * FOUT) return;
    int e = t / FOUT;
    int c = t - e * FOUT;
    int s, d; float w;
    if (e < NEDGES) { s = g_src[e]; d = g_dst[e]; w = g_norm[e]; }
    else { s = d = e - NEDGES; float dv = g_dis[s]; w = dv * dv; }
    atomicAdd(&g_a2[(size_t)d * FOUT + c], w * g_h2[(size_t)s * FOUT + c]);
}

// ---------------- post2: out = a2 + b2 ----------------
__global__ void k_post2(const float* __restrict__ b2, float* __restrict__ out) {
    int i = blockIdx.x * blockDim.x + threadIdx.x;
    if (i >= NNODES * FOUT) return;
    int v = i / FOUT;
    int c = i - v * FOUT;
    out[i] = g_a2[i] + b2[c];
}

// ---------------- launcher ----------------
extern "C" void kernel_launch(void* const* d_in, const int* in_sizes, int n_in,
                              void* d_out, int out_size) {
    const float* x  = nullptr;
    const int*   ei = nullptr;
    const float* W1 = nullptr;
    const float* b1 = nullptr;
    const float* W2 = nullptr;
    const float* b2 = nullptr;
    for (int i = 0; i < n_in; i++) {
        switch (in_sizes[i]) {
            case NNODES * FIN: x  = (const float*)d_in[i]; break;
            case 2 * NEDGES:   ei = (const int*)  d_in[i]; break;
            case FIN * FHID:   W1 = (const float*)d_in[i]; break;
            case FHID:         b1 = (const float*)d_in[i]; break;
            case FHID * FOUT:  W2 = (const float*)d_in[i]; break;
            case FOUT:         b2 = (const float*)d_in[i]; break;
        }
    }
    float* out = (float*)d_out;

    k_zflag <<<1, 1>>>();
    k_detect<<<(NEDGES + 255) / 256, 256>>>(ei);
    k_flag  <<<1, 1>>>();
    k_repack<<<(NEDGES + 255) / 256, 256>>>(ei);

    k_init  <<<(NNODES + 255) / 256, 256>>>();
    k_count <<<(NEDGES + 255) / 256, 256>>>();
    k_dis   <<<(NNODES + 255) / 256, 256>>>();
    k_norm  <<<(NEDGES + 255) / 256, 256>>>();
    k_zero  <<<2048, 256>>>();

    k_gemm1 <<<NNODES, FHID>>>(x, W1);
    k_edge1 <<<(NTOT * FHID + 255) / 256, 256>>>();
    k_post1 <<<(NNODES * FHID + 255) / 256, 256>>>(b1);

    k_gemm2 <<<NNODES, 64>>>(W2);
    k_edge2 <<<(NTOT * FOUT + 255) / 256, 256>>>();
    k_post2 <<<(NNODES * FOUT + 255) / 256, 256>>>(b2, out);
}

// round 5
// speedup vs baseline: 3.5909x; 3.5909x over previous
#include <cuda_runtime.h>
#include <cuda_bf16.h>
#include <cstdint>

#define NNODES 100000
#define NEDGES 1600000
#define NTOT   (NEDGES + NNODES)   // edges + self loops
#define FIN    128
#define FHID   128
#define FOUT   40

// ---------------- device scratch ----------------
__device__ float g_h1 [(size_t)NNODES * FHID];   // x @ W1
__device__ float g_h1b[(size_t)NNODES * FHID];   // relu(agg1 + b1)
__device__ float g_h2 [(size_t)NNODES * FOUT];   // h1b @ W2
__device__ int   g_src[NEDGES];
__device__ int   g_dst[NEDGES];
__device__ int   g_deg[NNODES];
__device__ int   g_cur[NNODES];
__device__ float g_dis[NNODES];
__device__ int   g_off[NNODES + 1];
__device__ int2  g_srcw[NTOT];                   // {src, bits(dis[src])} grouped by dst
__device__ int   g_oddzero;
__device__ int   g_is64;

// ---------------- edge-index format detection (int32 vs int64) --------------
__global__ void k_zflag() { g_oddzero = 0; }

__global__ void k_detect(const int* __restrict__ ei) {
    int i = blockIdx.x * blockDim.x + threadIdx.x;
    if (i < NEDGES) {
        // int64 little-endian buffer => every odd 32-bit word is 0
        if (ei[2 * i + 1] == 0) atomicAdd(&g_oddzero, 1);
    }
}

__global__ void k_flag() { g_is64 = (g_oddzero > 1000000) ? 1 : 0; }

__global__ void k_repack(const int* __restrict__ ei) {
    int e = blockIdx.x * blockDim.x + threadIdx.x;
    if (e >= NEDGES) return;
    if (g_is64) {
        g_src[e] = ei[2 * e];                 // low word of row[e]
        g_dst[e] = ei[2 * NEDGES + 2 * e];    // low word of col[e]
    } else {
        g_src[e] = ei[e];
        g_dst[e] = ei[NEDGES + e];
    }
}

// ---------------- degree / dis ----------------
__global__ void k_init() {
    int v = blockIdx.x * blockDim.x + threadIdx.x;
    if (v < NNODES) { g_deg[v] = 1; g_cur[v] = 0; }   // 1 = self loop
}

__global__ void k_count() {
    int e = blockIdx.x * blockDim.x + threadIdx.x;
    if (e < NEDGES) atomicAdd(&g_deg[g_dst[e]], 1);
}

__global__ void k_dis() {
    int v = blockIdx.x * blockDim.x + threadIdx.x;
    if (v < NNODES) g_dis[v] = rsqrtf((float)g_deg[v]);
}

// single-block exclusive scan over g_deg -> g_off
__global__ void k_scan() {
    __shared__ int sums[1024];
    const int CH = (NNODES + 1023) / 1024;   // 98
    int t = threadIdx.x;
    int begin = t * CH;
    int end = begin + CH; if (end > NNODES) end = NNODES;
    if (begin > NNODES) begin = NNODES;
    int s = 0;
    for (int i = begin; i < end; i++) s += g_deg[i];
    sums[t] = s;
    __syncthreads();
    for (int off = 1; off < 1024; off <<= 1) {
        int add = (t >= off) ? sums[t - off] : 0;
        __syncthreads();
        sums[t] += add;
        __syncthreads();
    }
    int run = (t == 0) ? 0 : sums[t - 1];
    for (int i = begin; i < end; i++) { g_off[i] = run; run += g_deg[i]; }
    if (t == 1023) g_off[NNODES] = NTOT;
}

__global__ void k_scatter() {
    int i = blockIdx.x * blockDim.x + threadIdx.x;
    if (i >= NTOT) return;
    int s, d;
    if (i < NEDGES) { s = g_src[i]; d = g_dst[i]; }
    else            { s = d = i - NEDGES; }
    int pos = g_off[d] + atomicAdd(&g_cur[d], 1);
    g_srcw[pos] = make_int2(s, __float_as_int(g_dis[s]));
}

// ---------------- GEMM1: h1 = x @ W1   (tiled 32x128, microtile 4x8) --------
__global__ __launch_bounds__(128) void k_gemm1(const float* __restrict__ x,
                                               const float* __restrict__ W) {
    __shared__ __align__(16) float xsT[128][36];   // [k][row], padded
    int t = threadIdx.x;
    int row0 = blockIdx.x * 32;
#pragma unroll
    for (int i = 0; i < 32; i++)
        xsT[t][i] = x[(size_t)(row0 + i) * FIN + t];
    __syncthreads();

    int tx = t & 15;   // col group (8 cols)
    int ty = t >> 4;   // row group (4 rows)
    float acc[4][8];
#pragma unroll
    for (int r = 0; r < 4; r++)
#pragma unroll
        for (int c = 0; c < 8; c++) acc[r][c] = 0.f;

    const float* Wc = W + tx * 8;
#pragma unroll 4
    for (int k = 0; k < 128; k++) {
        float a[4], b[8];
        *(float4*)a      = *(const float4*)&xsT[k][ty * 4];
        *(float4*)&b[0]  = *(const float4*)&Wc[k * FHID];
        *(float4*)&b[4]  = *(const float4*)&Wc[k * FHID + 4];
#pragma unroll
        for (int r = 0; r < 4; r++)
#pragma unroll
            for (int c = 0; c < 8; c++) acc[r][c] += a[r] * b[c];
    }
#pragma unroll
    for (int r = 0; r < 4; r++) {
        float* dst = g_h1 + (size_t)(row0 + ty * 4 + r) * FHID + tx * 8;
        *(float4*)dst       = make_float4(acc[r][0], acc[r][1], acc[r][2], acc[r][3]);
        *(float4*)(dst + 4) = make_float4(acc[r][4], acc[r][5], acc[r][6], acc[r][7]);
    }
}

// ---------------- agg1: h1b = relu(dis[v] * sum dis[s]*h1[s] + b1) ----------
// one warp per node, lane covers 4 features (float4)
__global__ __launch_bounds__(256) void k_agg1(const float* __restrict__ b1) {
    int w = blockIdx.x * 8 + (threadIdx.x >> 5);
    int lane = threadIdx.x & 31;
    if (w >= NNODES) return;
    int j = g_off[w], end = g_off[w + 1];
    float4 acc = make_float4(0.f, 0.f, 0.f, 0.f);
    for (; j + 2 <= end; j += 2) {
        int2 e0 = g_srcw[j], e1 = g_srcw[j + 1];
        float4 v0 = ((const float4*)(g_h1 + (size_t)e0.x * FHID))[lane];
        float4 v1 = ((const float4*)(g_h1 + (size_t)e1.x * FHID))[lane];
        float w0 = __int_as_float(e0.y), w1 = __int_as_float(e1.y);
        acc.x += w0 * v0.x + w1 * v1.x;
        acc.y += w0 * v0.y + w1 * v1.y;
        acc.z += w0 * v0.z + w1 * v1.z;
        acc.w += w0 * v0.w + w1 * v1.w;
    }
    if (j < end) {
        int2 e0 = g_srcw[j];
        float4 v0 = ((const float4*)(g_h1 + (size_t)e0.x * FHID))[lane];
        float w0 = __int_as_float(e0.y);
        acc.x += w0 * v0.x; acc.y += w0 * v0.y;
        acc.z += w0 * v0.z; acc.w += w0 * v0.w;
    }
    float dv = g_dis[w];
    float4 bb = ((const float4*)b1)[lane];
    float4 r;
    r.x = fmaxf(fmaf(dv, acc.x, bb.x), 0.f);
    r.y = fmaxf(fmaf(dv, acc.y, bb.y), 0.f);
    r.z = fmaxf(fmaf(dv, acc.z, bb.z), 0.f);
    r.w = fmaxf(fmaf(dv, acc.w, bb.w), 0.f);
    ((float4*)(g_h1b + (size_t)w * FHID))[lane] = r;
}

// ---------------- GEMM2: h2 = h1b @ W2  (128 -> 40) ----------------
__global__ __launch_bounds__(160) void k_gemm2(const float* __restrict__ W2) {
    __shared__ float xs[32][132];                 // FIXED: full 128-col rows (+pad)
    __shared__ __align__(16) float ws[128 * 40];
    int t = threadIdx.x;
    int row0 = blockIdx.x * 32;
    for (int i = t; i < 128 * 40; i += 160) ws[i] = W2[i];
    for (int e = t; e < 32 * 128; e += 160) {
        int r = e >> 7, k = e & 127;
        xs[r][k] = g_h1b[(size_t)(row0 + r) * FHID + k];
    }
    __syncthreads();

    int row = t & 31;
    int cy = t >> 5;           // 0..4 -> cols cy*8..cy*8+7
    float acc[8];
#pragma unroll
    for (int c = 0; c < 8; c++) acc[c] = 0.f;
#pragma unroll 4
    for (int k = 0; k < 128; k++) {
        float a = xs[row][k];
        float b[8];
        *(float4*)&b[0] = *(const float4*)&ws[k * 40 + cy * 8];
        *(float4*)&b[4] = *(const float4*)&ws[k * 40 + cy * 8 + 4];
#pragma unroll
        for (int c = 0; c < 8; c++) acc[c] += a * b[c];
    }
    float* dst = g_h2 + (size_t)(row0 + row) * FOUT + cy * 8;
#pragma unroll
    for (int c = 0; c < 8; c++) dst[c] = acc[c];
}

// ---------------- agg2: out = dis[v] * sum dis[s]*h2[s] + b2 ----------------
// one warp per node; lanes cover feats [0,32), lanes<8 also cover [32,40)
__global__ __launch_bounds__(256) void k_agg2(const float* __restrict__ b2,
                                              float* __restrict__ out) {
    int w = blockIdx.x * 8 + (threadIdx.x >> 5);
    int lane = threadIdx.x & 31;
    if (w >= NNODES) return;
    int j = g_off[w], end = g_off[w + 1];
    float accA = 0.f, accB = 0.f;
    for (; j + 2 <= end; j += 2) {
        int2 e0 = g_srcw[j], e1 = g_srcw[j + 1];
        const float* p0 = g_h2 + (size_t)e0.x * FOUT;
        const float* p1 = g_h2 + (size_t)e1.x * FOUT;
        float w0 = __int_as_float(e0.y), w1 = __int_as_float(e1.y);
        accA += w0 * p0[lane] + w1 * p1[lane];
        if (lane < 8) accB += w0 * p0[32 + lane] + w1 * p1[32 + lane];
    }
    if (j < end) {
        int2 e0 = g_srcw[j];
        const float* p0 = g_h2 + (size_t)e0.x * FOUT;
        float w0 = __int_as_float(e0.y);
        accA += w0 * p0[lane];
        if (lane < 8) accB += w0 * p0[32 + lane];
    }
    float dv = g_dis[w];
    out[(size_t)w * FOUT + lane] = fmaf(dv, accA, b2[lane]);
    if (lane < 8)
        out[(size_t)w * FOUT + 32 + lane] = fmaf(dv, accB, b2[32 + lane]);
}

// ---------------- launcher ----------------
extern "C" void kernel_launch(void* const* d_in, const int* in_sizes, int n_in,
                              void* d_out, int out_size) {
    const float* x  = nullptr;
    const int*   ei = nullptr;
    const float* W1 = nullptr;
    const float* b1 = nullptr;
    const float* W2 = nullptr;
    const float* b2 = nullptr;
    for (int i = 0; i < n_in; i++) {
        switch (in_sizes[i]) {
            case NNODES * FIN: x  = (const float*)d_in[i]; break;
            case 2 * NEDGES:   ei = (const int*)  d_in[i]; break;
            case FIN * FHID:   W1 = (const float*)d_in[i]; break;
            case FHID:         b1 = (const float*)d_in[i]; break;
            case FHID * FOUT:  W2 = (const float*)d_in[i]; break;
            case FOUT:         b2 = (const float*)d_in[i]; break;
        }
    }
    float* out = (float*)d_out;

    k_zflag  <<<1, 1>>>();
    k_detect <<<(NEDGES + 255) / 256, 256>>>(ei);
    k_flag   <<<1, 1>>>();
    k_repack <<<(NEDGES + 255) / 256, 256>>>(ei);

    k_init   <<<(NNODES + 255) / 256, 256>>>();
    k_count  <<<(NEDGES + 255) / 256, 256>>>();
    k_dis    <<<(NNODES + 255) / 256, 256>>>();
    k_scan   <<<1, 1024>>>();
    k_scatter<<<(NTOT + 255) / 256, 256>>>();

    k_gemm1  <<<NNODES / 32, 128>>>(x, W1);
    k_agg1   <<<(NNODES + 7) / 8, 256>>>(b1);
    k_gemm2  <<<NNODES / 32, 160>>>(W2);
    k_agg2   <<<(NNODES + 7) / 8, 256>>>(b2, out);
}